// round 5
// baseline (speedup 1.0000x reference)
#include <cuda_runtime.h>
#include <cuda_bf16.h>
#include <cstdint>

// Problem constants (fixed by the dataset)
#define NMAX   100000
#define EMAX   1600000
#define INCH   128
#define HIDCH  128
#define OUTCH  64

// ---------------- scratch (device globals; no allocation in kernel_launch) ----
__device__ float g_deg [NMAX];
__device__ float g_dinv[NMAX];
__device__ float g_h1  [(size_t)NMAX * HIDCH];
__device__ float g_agg1[(size_t)NMAX * HIDCH];
__device__ float g_hbuf[(size_t)NMAX * HIDCH];
__device__ float g_h2  [(size_t)NMAX * OUTCH];
__device__ float g_agg2[(size_t)NMAX * OUTCH];

// ---------------- tiny setup kernels -----------------------------------------
__global__ void deg_init_k(float* __restrict__ deg, int n) {
    int i = blockIdx.x * blockDim.x + threadIdx.x;
    if (i < n) deg[i] = 1.0f;   // self-loop
}

__global__ void deg_count_k(const int* __restrict__ dst, float* deg, int e, int n) {
    int i = blockIdx.x * blockDim.x + threadIdx.x;
    if (i < e) {
        int d = dst[i];
        if ((unsigned)d < (unsigned)n) atomicAdd(&deg[d], 1.0f);
    }
}

__global__ void dinv_k(const float* __restrict__ deg, float* __restrict__ dinv, int n) {
    int i = blockIdx.x * blockDim.x + threadIdx.x;
    if (i < n) dinv[i] = rsqrtf(deg[i]);
}

// ---------------- fp32 tiled GEMM with fused self-loop epilogue ---------------
// C[N, BN] = A[N, 128] @ W[128, BN];  writes H = C and AGG = C * dinv(row)^2
// BM=64 rows/block, BK=16, 256 threads, each thread 4 rows x TN cols.
template<int BN, int TN>
__global__ void __launch_bounds__(256)
gemm_selfloop_k(const float* __restrict__ A, const float* __restrict__ W,
                const float* __restrict__ dinv,
                float* __restrict__ H, float* __restrict__ AGG, int n)
{
    constexpr int BM = 64, BK = 16, K = 128;
    constexpr int AS_STRIDE = BM + 4;     // 68 floats: 272B rows, 16B-aligned
    __shared__ float As[BK * AS_STRIDE];
    __shared__ float Ws[BK * BN];

    const int tid = threadIdx.x;
    const int ty  = tid >> 4;             // 0..15 -> row group
    const int tx  = tid & 15;             // 0..15 -> col group
    const int rowBase = blockIdx.x * BM + ty * 4;
    const int colBase = tx * TN;

    // A-tile loader mapping: thread -> (row-in-tile, 4-wide k chunk)
    const int arow = tid >> 2;            // 0..63
    const int aq   = (tid & 3) * 4;       // 0,4,8,12
    const int grow = blockIdx.x * BM + arow;

    float acc[4][TN];
#pragma unroll
    for (int i = 0; i < 4; i++)
#pragma unroll
        for (int j = 0; j < TN; j++) acc[i][j] = 0.0f;

    for (int k0 = 0; k0 < K; k0 += BK) {
        // --- load A tile (transposed into smem: As[k][row]) ---
        float4 av = make_float4(0.f, 0.f, 0.f, 0.f);
        if (grow < n)
            av = *reinterpret_cast<const float4*>(A + (size_t)grow * K + k0 + aq);
        As[(aq + 0) * AS_STRIDE + arow] = av.x;
        As[(aq + 1) * AS_STRIDE + arow] = av.y;
        As[(aq + 2) * AS_STRIDE + arow] = av.z;
        As[(aq + 3) * AS_STRIDE + arow] = av.w;

        // --- load W tile (row-major, stride BN) ---
#pragma unroll
        for (int l = 0; l < BN / 64; l++) {
            int kk = tid >> 4;                       // 0..15
            int cc = (tid & 15) * (BN / 16) + l * 4; // covers all BN cols
            *reinterpret_cast<float4*>(&Ws[kk * BN + cc]) =
                *reinterpret_cast<const float4*>(W + (size_t)(k0 + kk) * BN + cc);
        }
        __syncthreads();

        // --- FMA core ---
#pragma unroll
        for (int kk = 0; kk < BK; kk++) {
            float4 ra = *reinterpret_cast<const float4*>(&As[kk * AS_STRIDE + ty * 4]);
            float rw[TN];
#pragma unroll
            for (int j = 0; j < TN; j += 4)
                *reinterpret_cast<float4*>(&rw[j]) =
                    *reinterpret_cast<const float4*>(&Ws[kk * BN + colBase + j]);
#pragma unroll
            for (int j = 0; j < TN; j++) {
                acc[0][j] += ra.x * rw[j];
                acc[1][j] += ra.y * rw[j];
                acc[2][j] += ra.z * rw[j];
                acc[3][j] += ra.w * rw[j];
            }
        }
        __syncthreads();
    }

    // --- epilogue: H = C, AGG = C * dinv^2 ---
#pragma unroll
    for (int i = 0; i < 4; i++) {
        int row = rowBase + i;
        if (row >= n) continue;
        float di  = dinv[row];
        float di2 = di * di;
#pragma unroll
        for (int j = 0; j < TN; j += 4) {
            float4 hv = make_float4(acc[i][j], acc[i][j + 1], acc[i][j + 2], acc[i][j + 3]);
            size_t off = (size_t)row * BN + colBase + j;
            *reinterpret_cast<float4*>(H + off) = hv;
            float4 avv = make_float4(hv.x * di2, hv.y * di2, hv.z * di2, hv.w * di2);
            *reinterpret_cast<float4*>(AGG + off) = avv;
        }
    }
}

// ---------------- edge scatter: agg[dst] += h[src] * dinv[src]*dinv[dst] ------
// C4 = float4 chunks per feature row (32 for 128ch, 16 for 64ch).
template<int C4>
__global__ void __launch_bounds__(256)
scatter_k(const int* __restrict__ src, const int* __restrict__ dst,
          const float* __restrict__ h, const float* __restrict__ dinv,
          float* __restrict__ agg, int e, int n)
{
    int tid  = blockIdx.x * blockDim.x + threadIdx.x;
    int edge = tid / C4;
    int lane = tid % C4;
    if (edge >= e) return;

    int s = src[edge];
    int d = dst[edge];
    if ((unsigned)s >= (unsigned)n || (unsigned)d >= (unsigned)n) return;
    float norm = dinv[s] * dinv[d];

    float4 v = reinterpret_cast<const float4*>(h)[(size_t)s * C4 + lane];
    float* a = agg + ((size_t)d * C4 + lane) * 4;
    atomicAdd(a + 0, v.x * norm);
    atomicAdd(a + 1, v.y * norm);
    atomicAdd(a + 2, v.z * norm);
    atomicAdd(a + 3, v.w * norm);
}

// ---------------- finalize: out = agg + bias (optional relu) ------------------
template<int C4, bool RELU>
__global__ void __launch_bounds__(256)
finalize_k(const float* __restrict__ agg, const float* __restrict__ bias,
           float* __restrict__ out, int total /* = n * C4 */)
{
    int tid = blockIdx.x * blockDim.x + threadIdx.x;
    if (tid >= total) return;
    int cc = tid % C4;
    float4 a = reinterpret_cast<const float4*>(agg)[tid];
    float4 b = reinterpret_cast<const float4*>(bias)[cc];
    float4 r = make_float4(a.x + b.x, a.y + b.y, a.z + b.z, a.w + b.w);
    if (RELU) {
        r.x = fmaxf(r.x, 0.0f); r.y = fmaxf(r.y, 0.0f);
        r.z = fmaxf(r.z, 0.0f); r.w = fmaxf(r.w, 0.0f);
    }
    reinterpret_cast<float4*>(out)[tid] = r;
}

// ---------------- launcher ----------------------------------------------------
extern "C" void kernel_launch(void* const* d_in, const int* in_sizes, int n_in,
                              void* d_out, int out_size)
{
    const float* x   = (const float*)d_in[0];
    const int*   ei  = (const int*)d_in[1];     // int32 on device (harness dtype set)
    const float* W1  = (const float*)d_in[2];
    const float* b1  = (const float*)d_in[3];
    const float* W2  = (const float*)d_in[4];
    const float* b2  = (const float*)d_in[5];
    float*       out = (float*)d_out;

    const int n = in_sizes[0] / INCH;
    const int e = in_sizes[1] / 2;
    const int* src = ei;
    const int* dst = ei + e;

    float *deg, *dinv, *h1, *agg1, *hbuf, *h2, *agg2;
    cudaGetSymbolAddress((void**)&deg,  g_deg);
    cudaGetSymbolAddress((void**)&dinv, g_dinv);
    cudaGetSymbolAddress((void**)&h1,   g_h1);
    cudaGetSymbolAddress((void**)&agg1, g_agg1);
    cudaGetSymbolAddress((void**)&hbuf, g_hbuf);
    cudaGetSymbolAddress((void**)&h2,   g_h2);
    cudaGetSymbolAddress((void**)&agg2, g_agg2);

    const int T = 256;

    // degrees + normalization
    deg_init_k <<<(n + T - 1) / T, T>>>(deg, n);
    deg_count_k<<<(e + T - 1) / T, T>>>(dst, deg, e, n);
    dinv_k     <<<(n + T - 1) / T, T>>>(deg, dinv, n);

    // ---- layer 1 ----
    gemm_selfloop_k<HIDCH, 8><<<(n + 63) / 64, 256>>>(x, W1, dinv, h1, agg1, n);

    {
        long long tot = (long long)e * (HIDCH / 4);
        scatter_k<HIDCH / 4><<<(unsigned)((tot + T - 1) / T), T>>>(src, dst, h1, dinv, agg1, e, n);
    }
    finalize_k<HIDCH / 4, true><<<(n * (HIDCH / 4) + T - 1) / T, T>>>(agg1, b1, hbuf, n * (HIDCH / 4));

    // ---- layer 2 ----
    gemm_selfloop_k<OUTCH, 4><<<(n + 63) / 64, 256>>>(hbuf, W2, dinv, h2, agg2, n);

    {
        long long tot = (long long)e * (OUTCH / 4);
        scatter_k<OUTCH / 4><<<(unsigned)((tot + T - 1) / T), T>>>(src, dst, h2, dinv, agg2, e, n);
    }
    finalize_k<OUTCH / 4, false><<<(n * (OUTCH / 4) + T - 1) / T, T>>>(agg2, b2, out, n * (OUTCH / 4));
}

// round 6
// speedup vs baseline: 2.6886x; 2.6886x over previous
#include <cuda_runtime.h>
#include <cuda_bf16.h>
#include <cstdint>

// Problem constants (fixed by the dataset)
#define NMAX   100000
#define EMAX   1600000
#define INCH   128
#define HIDCH  128
#define OUTCH  64

// ---------------- scratch (device globals; no allocation in kernel_launch) ----
__device__ int   g_counts [NMAX];
__device__ int   g_exc    [NMAX];
__device__ int   g_bsums  [512];
__device__ int   g_rowst  [NMAX + 1];
__device__ int   g_cursor [NMAX];
__device__ int   g_csrc   [EMAX];
__device__ float g_cnorm  [EMAX];
__device__ float g_dinv   [NMAX];
__device__ float g_h1  [(size_t)NMAX * HIDCH];
__device__ float g_hbuf[(size_t)NMAX * HIDCH];
__device__ float g_h2  [(size_t)NMAX * OUTCH];

// ---------------- setup kernels -----------------------------------------------
__global__ void zero_counts_k(int* __restrict__ counts, int n) {
    int i = blockIdx.x * blockDim.x + threadIdx.x;
    if (i < n) counts[i] = 0;
}

__global__ void count_k(const int* __restrict__ dst, int* counts, int e, int n) {
    int i = blockIdx.x * blockDim.x + threadIdx.x;
    if (i < e) {
        int d = dst[i];
        if ((unsigned)d < (unsigned)n) atomicAdd(&counts[d], 1);
    }
}

__global__ void dinv_k(const int* __restrict__ counts, float* __restrict__ dinv, int n) {
    int i = blockIdx.x * blockDim.x + threadIdx.x;
    if (i < n) dinv[i] = rsqrtf(1.0f + (float)counts[i]);   // +1 self-loop
}

// ---------------- exclusive scan (3 kernels, 256-wide blocks) -------------------
__global__ void scan_block_k(const int* __restrict__ counts, int* __restrict__ exc,
                             int* __restrict__ bsums, int n) {
    __shared__ int sh[256];
    int i = blockIdx.x * 256 + threadIdx.x;
    int v = (i < n) ? counts[i] : 0;
    sh[threadIdx.x] = v;
    __syncthreads();
#pragma unroll
    for (int off = 1; off < 256; off <<= 1) {
        int t = (threadIdx.x >= off) ? sh[threadIdx.x - off] : 0;
        __syncthreads();
        sh[threadIdx.x] += t;
        __syncthreads();
    }
    if (i < n) exc[i] = sh[threadIdx.x] - v;
    if (threadIdx.x == 255) bsums[blockIdx.x] = sh[255];
}

__global__ void scan_sums_k(int* __restrict__ bsums, int nb) {
    __shared__ int sh[512];
    int v = (threadIdx.x < nb) ? bsums[threadIdx.x] : 0;
    sh[threadIdx.x] = v;
    __syncthreads();
#pragma unroll
    for (int off = 1; off < 512; off <<= 1) {
        int t = (threadIdx.x >= off) ? sh[threadIdx.x - off] : 0;
        __syncthreads();
        sh[threadIdx.x] += t;
        __syncthreads();
    }
    if (threadIdx.x < nb) bsums[threadIdx.x] = sh[threadIdx.x] - v;  // exclusive
}

__global__ void scan_add_k(const int* __restrict__ exc, const int* __restrict__ bsums,
                           int* __restrict__ rowst, int* __restrict__ cursor,
                           int n, int e) {
    int i = blockIdx.x * 256 + threadIdx.x;
    if (i < n) {
        int r = exc[i] + bsums[i >> 8];
        rowst[i]  = r;
        cursor[i] = r;
    }
    if (i == 0) rowst[n] = e;
}

// ---------------- CSR fill ------------------------------------------------------
__global__ void fill_k(const int* __restrict__ src, const int* __restrict__ dst,
                       const float* __restrict__ dinv,
                       int* cursor, int* __restrict__ csrc, float* __restrict__ cnorm,
                       int e, int n) {
    int i = blockIdx.x * blockDim.x + threadIdx.x;
    if (i >= e) return;
    int s = src[i], d = dst[i];
    if ((unsigned)s >= (unsigned)n || (unsigned)d >= (unsigned)n) return;
    int pos = atomicAdd(&cursor[d], 1);
    csrc[pos]  = s;
    cnorm[pos] = dinv[s] * dinv[d];
}

// ---------------- fp32 tiled GEMM: H = A @ W ------------------------------------
// BM=64 rows/block, BK=16, 256 threads, each thread 4 rows x TN cols.
template<int BN, int TN>
__global__ void __launch_bounds__(256)
gemm_k(const float* __restrict__ A, const float* __restrict__ W,
       float* __restrict__ H, int n)
{
    constexpr int BM = 64, BK = 16, K = 128;
    constexpr int AS_STRIDE = BM + 4;
    __shared__ float As[BK * AS_STRIDE];
    __shared__ float Ws[BK * BN];

    const int tid = threadIdx.x;
    const int ty  = tid >> 4;
    const int tx  = tid & 15;
    const int rowBase = blockIdx.x * BM + ty * 4;
    const int colBase = tx * TN;

    const int arow = tid >> 2;
    const int aq   = (tid & 3) * 4;
    const int grow = blockIdx.x * BM + arow;

    float acc[4][TN];
#pragma unroll
    for (int i = 0; i < 4; i++)
#pragma unroll
        for (int j = 0; j < TN; j++) acc[i][j] = 0.0f;

    for (int k0 = 0; k0 < K; k0 += BK) {
        float4 av = make_float4(0.f, 0.f, 0.f, 0.f);
        if (grow < n)
            av = *reinterpret_cast<const float4*>(A + (size_t)grow * K + k0 + aq);
        As[(aq + 0) * AS_STRIDE + arow] = av.x;
        As[(aq + 1) * AS_STRIDE + arow] = av.y;
        As[(aq + 2) * AS_STRIDE + arow] = av.z;
        As[(aq + 3) * AS_STRIDE + arow] = av.w;

#pragma unroll
        for (int l = 0; l < BN / 64; l++) {
            int kk = tid >> 4;
            int cc = (tid & 15) * (BN / 16) + l * 4;
            *reinterpret_cast<float4*>(&Ws[kk * BN + cc]) =
                *reinterpret_cast<const float4*>(W + (size_t)(k0 + kk) * BN + cc);
        }
        __syncthreads();

#pragma unroll
        for (int kk = 0; kk < BK; kk++) {
            float4 ra = *reinterpret_cast<const float4*>(&As[kk * AS_STRIDE + ty * 4]);
            float rw[TN];
#pragma unroll
            for (int j = 0; j < TN; j += 4)
                *reinterpret_cast<float4*>(&rw[j]) =
                    *reinterpret_cast<const float4*>(&Ws[kk * BN + colBase + j]);
#pragma unroll
            for (int j = 0; j < TN; j++) {
                acc[0][j] += ra.x * rw[j];
                acc[1][j] += ra.y * rw[j];
                acc[2][j] += ra.z * rw[j];
                acc[3][j] += ra.w * rw[j];
            }
        }
        __syncthreads();
    }

#pragma unroll
    for (int i = 0; i < 4; i++) {
        int row = rowBase + i;
        if (row >= n) continue;
#pragma unroll
        for (int j = 0; j < TN; j += 4) {
            float4 hv = make_float4(acc[i][j], acc[i][j + 1], acc[i][j + 2], acc[i][j + 3]);
            *reinterpret_cast<float4*>(H + (size_t)row * BN + colBase + j) = hv;
        }
    }
}

// ---------------- gather: out[d] = sum_{e in row(d)} h[src_e]*norm_e
//                          + h[d]*dinv[d]^2 + bias   (optional relu)
// C4 = float4 chunks per row (32 for 128ch, 16 for 64ch). 32/C4 nodes per warp.
template<int C4, bool RELU>
__global__ void __launch_bounds__(256)
gather_k(const int* __restrict__ rowst, const int* __restrict__ csrc,
         const float* __restrict__ cnorm, const float* __restrict__ h,
         const float* __restrict__ dinv, const float* __restrict__ bias,
         float* __restrict__ out, int n)
{
    constexpr int NPW = 32 / C4;                 // nodes per warp
    const int gtid = blockIdx.x * 256 + threadIdx.x;
    const int warp = gtid >> 5;
    const int lane = threadIdx.x & 31;
    const int sub  = lane / C4;                  // node slot within warp
    const int ln   = lane % C4;                  // float4 chunk index
    const int node = warp * NPW + sub;
    if (node >= n) return;

    const float4* __restrict__ h4 = reinterpret_cast<const float4*>(h);
    const float4* __restrict__ b4 = reinterpret_cast<const float4*>(bias);

    const int start = rowst[node];
    const int end   = rowst[node + 1];

    float ax = 0.f, ay = 0.f, az = 0.f, aw = 0.f;

    int j = start;
    for (; j + 4 <= end; j += 4) {
        int   s0 = csrc[j],     s1 = csrc[j + 1], s2 = csrc[j + 2], s3 = csrc[j + 3];
        float n0 = cnorm[j],    n1 = cnorm[j + 1], n2 = cnorm[j + 2], n3 = cnorm[j + 3];
        float4 v0 = h4[(size_t)s0 * C4 + ln];
        float4 v1 = h4[(size_t)s1 * C4 + ln];
        float4 v2 = h4[(size_t)s2 * C4 + ln];
        float4 v3 = h4[(size_t)s3 * C4 + ln];
        ax += v0.x * n0 + v1.x * n1 + v2.x * n2 + v3.x * n3;
        ay += v0.y * n0 + v1.y * n1 + v2.y * n2 + v3.y * n3;
        az += v0.z * n0 + v1.z * n1 + v2.z * n2 + v3.z * n3;
        aw += v0.w * n0 + v1.w * n1 + v2.w * n2 + v3.w * n3;
    }
    for (; j < end; ++j) {
        int s = csrc[j];
        float nn = cnorm[j];
        float4 v = h4[(size_t)s * C4 + ln];
        ax += v.x * nn; ay += v.y * nn; az += v.z * nn; aw += v.w * nn;
    }

    // self-loop + bias
    float di  = dinv[node];
    float di2 = di * di;
    float4 hv = h4[(size_t)node * C4 + ln];
    float4 bb = b4[ln];
    ax += hv.x * di2 + bb.x;
    ay += hv.y * di2 + bb.y;
    az += hv.z * di2 + bb.z;
    aw += hv.w * di2 + bb.w;
    if (RELU) {
        ax = fmaxf(ax, 0.f); ay = fmaxf(ay, 0.f);
        az = fmaxf(az, 0.f); aw = fmaxf(aw, 0.f);
    }
    reinterpret_cast<float4*>(out)[(size_t)node * C4 + ln] = make_float4(ax, ay, az, aw);
}

// ---------------- launcher ----------------------------------------------------
extern "C" void kernel_launch(void* const* d_in, const int* in_sizes, int n_in,
                              void* d_out, int out_size)
{
    const float* x   = (const float*)d_in[0];
    const int*   ei  = (const int*)d_in[1];
    const float* W1  = (const float*)d_in[2];
    const float* b1  = (const float*)d_in[3];
    const float* W2  = (const float*)d_in[4];
    const float* b2  = (const float*)d_in[5];
    float*       out = (float*)d_out;

    const int n = in_sizes[0] / INCH;
    const int e = in_sizes[1] / 2;
    const int* src = ei;
    const int* dst = ei + e;

    int *counts, *exc, *bsums, *rowst, *cursor, *csrc;
    float *cnorm, *dinv, *h1, *hbuf, *h2;
    cudaGetSymbolAddress((void**)&counts, g_counts);
    cudaGetSymbolAddress((void**)&exc,    g_exc);
    cudaGetSymbolAddress((void**)&bsums,  g_bsums);
    cudaGetSymbolAddress((void**)&rowst,  g_rowst);
    cudaGetSymbolAddress((void**)&cursor, g_cursor);
    cudaGetSymbolAddress((void**)&csrc,   g_csrc);
    cudaGetSymbolAddress((void**)&cnorm,  g_cnorm);
    cudaGetSymbolAddress((void**)&dinv,   g_dinv);
    cudaGetSymbolAddress((void**)&h1,     g_h1);
    cudaGetSymbolAddress((void**)&hbuf,   g_hbuf);
    cudaGetSymbolAddress((void**)&h2,     g_h2);

    const int T = 256;
    const int nb = (n + 255) / 256;

    // ---- degree + CSR build ----
    zero_counts_k<<<(n + T - 1) / T, T>>>(counts, n);
    count_k      <<<(e + T - 1) / T, T>>>(dst, counts, e, n);
    dinv_k       <<<(n + T - 1) / T, T>>>(counts, dinv, n);
    scan_block_k <<<nb, 256>>>(counts, exc, bsums, n);
    scan_sums_k  <<<1, 512>>>(bsums, nb);
    scan_add_k   <<<nb, 256>>>(exc, bsums, rowst, cursor, n, e);
    fill_k       <<<(e + T - 1) / T, T>>>(src, dst, dinv, cursor, csrc, cnorm, e, n);

    // ---- layer 1: h1 = x@W1 ; hbuf = relu(gather(h1) + self + b1) ----
    gemm_k<HIDCH, 8><<<(n + 63) / 64, 256>>>(x, W1, h1, n);
    {
        constexpr int C4 = HIDCH / 4;            // 32 -> 1 node per warp
        int warps = n;                            // NPW = 1
        gather_k<C4, true><<<(warps * 32 + 255) / 256, 256>>>(
            rowst, csrc, cnorm, h1, dinv, b1, hbuf, n);
    }

    // ---- layer 2: h2 = hbuf@W2 ; out = gather(h2) + self + b2 ----
    gemm_k<OUTCH, 4><<<(n + 63) / 64, 256>>>(hbuf, W2, h2, n);
    {
        constexpr int C4 = OUTCH / 4;            // 16 -> 2 nodes per warp
        int warps = (n + 1) / 2;
        gather_k<C4, false><<<(warps * 32 + 255) / 256, 256>>>(
            rowst, csrc, cnorm, h2, dinv, b2, out, n);
    }
}

// round 10
// speedup vs baseline: 3.1935x; 1.1878x over previous
#include <cuda_runtime.h>
#include <cuda_bf16.h>
#include <cstdint>

// Problem constants (fixed by the dataset)
#define NMAX   100000
#define EMAX   1600000
#define INCH   128
#define HIDCH  128
#define OUTCH  64

// ---------------- scratch (device globals; no allocation in kernel_launch) ----
__device__ int   g_counts [NMAX];
__device__ int   g_exc    [NMAX];
__device__ int   g_bsums  [512];
__device__ int   g_rowst  [NMAX + 1];
__device__ int   g_cursor [NMAX];
__device__ int   g_csrc   [EMAX];
__device__ float g_cnorm  [EMAX];
__device__ float g_dinv   [NMAX];
__device__ float g_h1  [(size_t)NMAX * HIDCH];
__device__ float g_hbuf[(size_t)NMAX * HIDCH];
__device__ float g_h2  [(size_t)NMAX * OUTCH];

// ---------------- setup kernels -----------------------------------------------
__global__ void zero_counts_k(int* __restrict__ counts, int n) {
    int i = blockIdx.x * blockDim.x + threadIdx.x;
    if (i < n) counts[i] = 0;
}

__global__ void count_k(const int* __restrict__ dst, int* counts, int e, int n) {
    int i = blockIdx.x * blockDim.x + threadIdx.x;
    if (i < e) {
        int d = dst[i];
        if ((unsigned)d < (unsigned)n) atomicAdd(&counts[d], 1);
    }
}

__global__ void dinv_k(const int* __restrict__ counts, float* __restrict__ dinv, int n) {
    int i = blockIdx.x * blockDim.x + threadIdx.x;
    if (i < n) dinv[i] = rsqrtf(1.0f + (float)counts[i]);   // +1 self-loop
}

// ---------------- exclusive scan (3 kernels, 256-wide blocks) -------------------
__global__ void scan_block_k(const int* __restrict__ counts, int* __restrict__ exc,
                             int* __restrict__ bsums, int n) {
    __shared__ int sh[256];
    int i = blockIdx.x * 256 + threadIdx.x;
    int v = (i < n) ? counts[i] : 0;
    sh[threadIdx.x] = v;
    __syncthreads();
#pragma unroll
    for (int off = 1; off < 256; off <<= 1) {
        int t = (threadIdx.x >= off) ? sh[threadIdx.x - off] : 0;
        __syncthreads();
        sh[threadIdx.x] += t;
        __syncthreads();
    }
    if (i < n) exc[i] = sh[threadIdx.x] - v;
    if (threadIdx.x == 255) bsums[blockIdx.x] = sh[255];
}

__global__ void scan_sums_k(int* __restrict__ bsums, int nb) {
    __shared__ int sh[512];
    int v = (threadIdx.x < nb) ? bsums[threadIdx.x] : 0;
    sh[threadIdx.x] = v;
    __syncthreads();
#pragma unroll
    for (int off = 1; off < 512; off <<= 1) {
        int t = (threadIdx.x >= off) ? sh[threadIdx.x - off] : 0;
        __syncthreads();
        sh[threadIdx.x] += t;
        __syncthreads();
    }
    if (threadIdx.x < nb) bsums[threadIdx.x] = sh[threadIdx.x] - v;  // exclusive
}

__global__ void scan_add_k(const int* __restrict__ exc, const int* __restrict__ bsums,
                           int* __restrict__ rowst, int* __restrict__ cursor,
                           int n, int e) {
    int i = blockIdx.x * 256 + threadIdx.x;
    if (i < n) {
        int r = exc[i] + bsums[i >> 8];
        rowst[i]  = r;
        cursor[i] = r;
    }
    if (i == 0) rowst[n] = e;
}

// ---------------- CSR fill ------------------------------------------------------
__global__ void fill_k(const int* __restrict__ src, const int* __restrict__ dst,
                       const float* __restrict__ dinv,
                       int* cursor, int* __restrict__ csrc, float* __restrict__ cnorm,
                       int e, int n) {
    int i = blockIdx.x * blockDim.x + threadIdx.x;
    if (i >= e) return;
    int s = src[i], d = dst[i];
    if ((unsigned)s >= (unsigned)n || (unsigned)d >= (unsigned)n) return;
    int pos = atomicAdd(&cursor[d], 1);
    csrc[pos]  = s;
    cnorm[pos] = dinv[s] * dinv[d];
}

// ---------------- fp32 GEMM, 8x8 register tile: H = A[n,128] @ W[128,BN] -------
// 256 threads. Split-tile addressing: thread covers rows {ty*4..+3, BM/2+ty*4..+3}
// and cols {tx*4..+3, BN/2+tx*4..+3} so all LDS.128 are contiguous/broadcast.
template<int BM, int BN>
__global__ void __launch_bounds__(256)
gemm_k(const float* __restrict__ A, const float* __restrict__ W,
       float* __restrict__ H, int n)
{
    constexpr int K   = 128;
    constexpr int BK  = 16;
    constexpr int BMP = BM + 4;              // pad: STS near-conflict-free, 16B-aligned
    constexpr int COLG = BN / 8;             // col groups (16 or 8)
    static_assert((BM / 8) * COLG == 256, "256 threads");

    __shared__ float As[BK * BMP];           // transposed: As[k][row]
    __shared__ float Ws[BK * BN];            // Ws[k][col]

    const int tid = threadIdx.x;
    const int ty  = tid / COLG;
    const int tx  = tid % COLG;

    float acc[8][8];
#pragma unroll
    for (int i = 0; i < 8; i++)
#pragma unroll
        for (int j = 0; j < 8; j++) acc[i][j] = 0.0f;

    for (int k0 = 0; k0 < K; k0 += BK) {
        // --- load A tile: BM x 16 floats, transposed into As ---
#pragma unroll
        for (int p = 0; p < BM / 64; p++) {
            int idx  = p * 256 + tid;
            int row  = idx >> 2;
            int q    = (idx & 3) * 4;
            int grow = blockIdx.x * BM + row;
            float4 av = make_float4(0.f, 0.f, 0.f, 0.f);
            if (grow < n)
                av = *reinterpret_cast<const float4*>(A + (size_t)grow * K + k0 + q);
            As[(q + 0) * BMP + row] = av.x;
            As[(q + 1) * BMP + row] = av.y;
            As[(q + 2) * BMP + row] = av.z;
            As[(q + 3) * BMP + row] = av.w;
        }

        // --- load W tile: 16 x BN floats ---
#pragma unroll
        for (int p = 0; p < BN / 64; p++) {
            int idx = p * 256 + tid;
            int kk  = idx / (BN / 4);
            int cq  = (idx % (BN / 4)) * 4;
            *reinterpret_cast<float4*>(&Ws[kk * BN + cq]) =
                *reinterpret_cast<const float4*>(W + (size_t)(k0 + kk) * BN + cq);
        }
        __syncthreads();

        // --- FMA core: 64 FMA per thread per kk, 64B LDS ---
#pragma unroll
        for (int kk = 0; kk < BK; kk++) {
            float4 a0 = *reinterpret_cast<const float4*>(&As[kk * BMP + ty * 4]);
            float4 a1 = *reinterpret_cast<const float4*>(&As[kk * BMP + BM / 2 + ty * 4]);
            float4 w0 = *reinterpret_cast<const float4*>(&Ws[kk * BN + tx * 4]);
            float4 w1 = *reinterpret_cast<const float4*>(&Ws[kk * BN + BN / 2 + tx * 4]);
            float ar[8] = {a0.x, a0.y, a0.z, a0.w, a1.x, a1.y, a1.z, a1.w};
            float wr[8] = {w0.x, w0.y, w0.z, w0.w, w1.x, w1.y, w1.z, w1.w};
#pragma unroll
            for (int i = 0; i < 8; i++)
#pragma unroll
                for (int j = 0; j < 8; j++)
                    acc[i][j] += ar[i] * wr[j];
        }
        __syncthreads();
    }

    // --- epilogue: write 2x2 blocks of 4x4 ---
#pragma unroll
    for (int i = 0; i < 8; i++) {
        int rloc = (i < 4) ? (ty * 4 + i) : (BM / 2 + ty * 4 + i - 4);
        int row  = blockIdx.x * BM + rloc;
        if (row >= n) continue;
        float4 v0 = make_float4(acc[i][0], acc[i][1], acc[i][2], acc[i][3]);
        float4 v1 = make_float4(acc[i][4], acc[i][5], acc[i][6], acc[i][7]);
        *reinterpret_cast<float4*>(H + (size_t)row * BN + tx * 4)           = v0;
        *reinterpret_cast<float4*>(H + (size_t)row * BN + BN / 2 + tx * 4)  = v1;
    }
}

// ---------------- gather: out[d] = sum_{e in row(d)} h[src_e]*norm_e
//                          + h[d]*dinv[d]^2 + bias   (optional relu)
// C4 = float4 chunks per row (32 for 128ch, 16 for 64ch). 32/C4 nodes per warp.
template<int C4, bool RELU>
__global__ void __launch_bounds__(256)
gather_k(const int* __restrict__ rowst, const int* __restrict__ csrc,
         const float* __restrict__ cnorm, const float* __restrict__ h,
         const float* __restrict__ dinv, const float* __restrict__ bias,
         float* __restrict__ out, int n)
{
    constexpr int NPW = 32 / C4;                 // nodes per warp
    const int gtid = blockIdx.x * 256 + threadIdx.x;
    const int warp = gtid >> 5;
    const int lane = threadIdx.x & 31;
    const int sub  = lane / C4;                  // node slot within warp
    const int ln   = lane % C4;                  // float4 chunk index
    const int node = warp * NPW + sub;
    if (node >= n) return;

    const float4* __restrict__ h4 = reinterpret_cast<const float4*>(h);
    const float4* __restrict__ b4 = reinterpret_cast<const float4*>(bias);

    const int start = rowst[node];
    const int end   = rowst[node + 1];

    float ax = 0.f, ay = 0.f, az = 0.f, aw = 0.f;

    int j = start;
    for (; j + 4 <= end; j += 4) {
        int   s0 = csrc[j],     s1 = csrc[j + 1], s2 = csrc[j + 2], s3 = csrc[j + 3];
        float n0 = cnorm[j],    n1 = cnorm[j + 1], n2 = cnorm[j + 2], n3 = cnorm[j + 3];
        float4 v0 = h4[(size_t)s0 * C4 + ln];
        float4 v1 = h4[(size_t)s1 * C4 + ln];
        float4 v2 = h4[(size_t)s2 * C4 + ln];
        float4 v3 = h4[(size_t)s3 * C4 + ln];
        ax += v0.x * n0 + v1.x * n1 + v2.x * n2 + v3.x * n3;
        ay += v0.y * n0 + v1.y * n1 + v2.y * n2 + v3.y * n3;
        az += v0.z * n0 + v1.z * n1 + v2.z * n2 + v3.z * n3;
        aw += v0.w * n0 + v1.w * n1 + v2.w * n2 + v3.w * n3;
    }
    for (; j < end; ++j) {
        int s = csrc[j];
        float nn = cnorm[j];
        float4 v = h4[(size_t)s * C4 + ln];
        ax += v.x * nn; ay += v.y * nn; az += v.z * nn; aw += v.w * nn;
    }

    // self-loop + bias
    float di  = dinv[node];
    float di2 = di * di;
    float4 hv = h4[(size_t)node * C4 + ln];
    float4 bb = b4[ln];
    ax += hv.x * di2 + bb.x;
    ay += hv.y * di2 + bb.y;
    az += hv.z * di2 + bb.z;
    aw += hv.w * di2 + bb.w;
    if (RELU) {
        ax = fmaxf(ax, 0.f); ay = fmaxf(ay, 0.f);
        az = fmaxf(az, 0.f); aw = fmaxf(aw, 0.f);
    }
    reinterpret_cast<float4*>(out)[(size_t)node * C4 + ln] = make_float4(ax, ay, az, aw);
}

// ---------------- launcher ----------------------------------------------------
extern "C" void kernel_launch(void* const* d_in, const int* in_sizes, int n_in,
                              void* d_out, int out_size)
{
    const float* x   = (const float*)d_in[0];
    const int*   ei  = (const int*)d_in[1];
    const float* W1  = (const float*)d_in[2];
    const float* b1  = (const float*)d_in[3];
    const float* W2  = (const float*)d_in[4];
    const float* b2  = (const float*)d_in[5];
    float*       out = (float*)d_out;

    const int n = in_sizes[0] / INCH;
    const int e = in_sizes[1] / 2;
    const int* src = ei;
    const int* dst = ei + e;

    int *counts, *exc, *bsums, *rowst, *cursor, *csrc;
    float *cnorm, *dinv, *h1, *hbuf, *h2;
    cudaGetSymbolAddress((void**)&counts, g_counts);
    cudaGetSymbolAddress((void**)&exc,    g_exc);
    cudaGetSymbolAddress((void**)&bsums,  g_bsums);
    cudaGetSymbolAddress((void**)&rowst,  g_rowst);
    cudaGetSymbolAddress((void**)&cursor, g_cursor);
    cudaGetSymbolAddress((void**)&csrc,   g_csrc);
    cudaGetSymbolAddress((void**)&cnorm,  g_cnorm);
    cudaGetSymbolAddress((void**)&dinv,   g_dinv);
    cudaGetSymbolAddress((void**)&h1,     g_h1);
    cudaGetSymbolAddress((void**)&hbuf,   g_hbuf);
    cudaGetSymbolAddress((void**)&h2,     g_h2);

    const int T = 256;
    const int nb = (n + 255) / 256;

    // ---- degree + CSR build ----
    zero_counts_k<<<(n + T - 1) / T, T>>>(counts, n);
    count_k      <<<(e + T - 1) / T, T>>>(dst, counts, e, n);
    dinv_k       <<<(n + T - 1) / T, T>>>(counts, dinv, n);
    scan_block_k <<<nb, 256>>>(counts, exc, bsums, n);
    scan_sums_k  <<<1, 512>>>(bsums, nb);
    scan_add_k   <<<nb, 256>>>(exc, bsums, rowst, cursor, n, e);
    fill_k       <<<(e + T - 1) / T, T>>>(src, dst, dinv, cursor, csrc, cnorm, e, n);

    // ---- layer 1: h1 = x@W1 ; hbuf = relu(gather(h1) + self + b1) ----
    gemm_k<128, HIDCH><<<(n + 127) / 128, 256>>>(x, W1, h1, n);
    {
        constexpr int C4 = HIDCH / 4;            // 32 -> 1 node per warp
        int warps = n;
        gather_k<C4, true><<<(warps * 32 + 255) / 256, 256>>>(
            rowst, csrc, cnorm, h1, dinv, b1, hbuf, n);
    }

    // ---- layer 2: h2 = hbuf@W2 ; out = gather(h2) + self + b2 ----
    gemm_k<256, OUTCH><<<(n + 255) / 256, 256>>>(hbuf, W2, h2, n);
    {
        constexpr int C4 = OUTCH / 4;            // 16 -> 2 nodes per warp
        int warps = (n + 1) / 2;
        gather_k<C4, false><<<(warps * 32 + 255) / 256, 256>>>(
            rowst, csrc, cnorm, h2, dinv, b2, out, n);
    }
}